// round 10
// baseline (speedup 1.0000x reference)
#include <cuda_runtime.h>
#include <cuda_fp16.h>
#include <cstdint>

// ============================================================
// Portable-PTX (base sm_103): ldmatrix + mma.sync fp16 (2-pass A-split)
// 3 CTAs/SM, M=64 rows per CTA, cp.async B pipeline (4-kstep units)
// fp32 ring-overlay staging for vectorized A-mix epilogue
// ============================================================
__device__ __forceinline__ uint32_t smem_u32(const void* p) {
    uint32_t a;
    asm("{ .reg .u64 t; cvta.to.shared.u64 t, %1; cvt.u32.u64 %0, t; }" : "=r"(a) : "l"(p));
    return a;
}
#define LDSM_X4(a0,a1,a2,a3,addr) \
    asm volatile("ldmatrix.sync.aligned.m8n8.x4.shared.b16 {%0,%1,%2,%3}, [%4];" \
        : "=r"(a0), "=r"(a1), "=r"(a2), "=r"(a3) : "r"(addr))
#define MMA_F16(c, a, b0, b1) \
    asm volatile("mma.sync.aligned.m16n8k16.row.col.f32.f16.f16.f32 " \
        "{%0,%1,%2,%3}, {%4,%5,%6,%7}, {%8,%9}, {%0,%1,%2,%3};" \
        : "+f"((c)[0]), "+f"((c)[1]), "+f"((c)[2]), "+f"((c)[3]) \
        : "r"((a)[0]), "r"((a)[1]), "r"((a)[2]), "r"((a)[3]), "r"(b0), "r"(b1))
__device__ __forceinline__ void cp16(uint32_t dst, const void* src) {
    asm volatile("cp.async.ca.shared.global [%0], [%1], 16;" :: "r"(dst), "l"(src));
}
#define CP_COMMIT()  asm volatile("cp.async.commit_group;" ::: "memory")
#define CP_WAIT(n)   asm volatile("cp.async.wait_group %0;" :: "n"(n) : "memory")

namespace {
constexpr int LDX  = 136;   // fp16 row stride (272 B -> LDSM conflict-free)
constexpr int LDF  = 132;   // fp32 staging row stride (conflict-free)
constexpr int ANN  = 12;    // max nnz per A row
constexpr int MROW = 64;    // rows per CTA tile (63 valid = 3 batches)
constexpr int RPC  = 63;
// dynamic smem offsets
constexpr int OFF_XH   = 0;            // [64][136] fp16 = 17408
constexpr int OFF_XL   = 17408;        // [64][136] fp16 = 17408
constexpr int OFF_B    = 34816;        // ring 2x16384 = 32768; fp32 Xf overlay [64][132] = 33792
constexpr int OFF_AW   = 68608;        // [3][21][12] f32 = 3024
constexpr int OFF_AI   = 71632;        // [3][21][12] u8  = 768
constexpr int OFF_ACNT = 72400;        // i32[64]  = 256
constexpr int OFF_OAC  = 72656;        // f32[192] = 768
constexpr int OFF_ROWN = 73424;        // u8[64]
constexpr int SMEM_SZ  = 73600;        // x3 CTAs ~ 221 KB < 228 KB
// fragment bases (1 frag = B-hi for one (kstep, n-tile); 256 B = 32 lanes x 8 B)
constexpr int FR_W1 = 0;      // 16 ks * 16 nt = 256
constexpr int FR_W2 = 256;    //  8 ks * 16 nt = 128
constexpr int FR_W3 = 384;    //  8 ks * 64 nt = 512
constexpr int NFRAG = 896;
} // namespace

// Per-lane B-hi fragments (fp16x2 pairs). 16 consecutive frags (one CTA k-step)
// = 4 KB contiguous -> bulk cp.async. L2-resident.
__device__ __align__(16) uint2 gWB[NFRAG][32];

__device__ __forceinline__ uint32_t pack_h2(float x, float y) {
    __half2 h = __floats2half2_rn(x, y);
    return *reinterpret_cast<uint32_t*>(&h);
}

// frag id = base + ks*NT + nt
__global__ void prep_frags(const float* __restrict__ W1,
                           const float* __restrict__ W2,
                           const float* __restrict__ W3) {
    const int id = blockIdx.x, l = threadIdx.x;
    const float* W; int ld, r, NT;
    if (id < 256)      { W = W1; ld = 128; r = id;       NT = 16; }
    else if (id < 384) { W = W2; ld = 128; r = id - 256; NT = 16; }
    else               { W = W3; ld = 512; r = id - 384; NT = 64; }
    const int nt = r % NT, ks = r / NT;
    const int n  = nt * 8 + (l >> 2);
    const int k0 = ks * 16 + (l & 3) * 2;
    float v[4];
    #pragma unroll
    for (int i = 0; i < 4; ++i)
        v[i] = W[(size_t)(k0 + (i >> 1) * 8 + (i & 1)) * ld + n];
    gWB[id][l] = make_uint2(pack_h2(v[0], v[1]), pack_h2(v[2], v[3]));
}

__global__ void __launch_bounds__(256, 3)
handnet_mma(const float* __restrict__ x,
            const float* __restrict__ A1, const float* __restrict__ A2,
            const float* __restrict__ A3,
            const float* __restrict__ b1, const float* __restrict__ b2,
            const float* __restrict__ b3,
            const float* __restrict__ fcW, const float* __restrict__ fcb,
            float* __restrict__ x3g, float* __restrict__ outg, int Btot)
{
    extern __shared__ unsigned char sm[];
    __half*  XH   = (__half*)(sm + OFF_XH);
    __half*  XL   = (__half*)(sm + OFF_XL);
    float*   Xf   = (float*)(sm + OFF_B);       // fp32 staging (overlays B ring)
    float*   Aw   = (float*)(sm + OFF_AW);
    uint8_t* Ai   = sm + OFF_AI;
    int*     Acnt = (int*)(sm + OFF_ACNT);
    float*   Oac  = (float*)(sm + OFF_OAC);
    uint8_t* rown = sm + OFF_ROWN;

    const int tid = threadIdx.x, lane = tid & 31, wid = tid >> 5;
    const int mg = wid >> 2, ng = wid & 3;        // 2 m-groups x 4 n-groups
    const int m0base = mg * 32;
    const int arow = m0base + (lane & 7) + ((lane >> 3) & 1) * 8;
    const int kadd = ((lane >> 4) & 1) * 8;
    const uint32_t xh = smem_u32(XH), xl = smem_u32(XL);
    const uint32_t smB = smem_u32(sm + OFF_B);

    const int b0row = blockIdx.x * RPC;
    const int rows_valid = min(RPC, Btot * 21 - b0row);

    // ---- setup ----
    if (tid < MROW) rown[tid] = (uint8_t)(tid % 21);
    if (tid < 63) {
        int L = tid / 21, n = tid % 21;
        const float* A = (L == 0) ? A1 : ((L == 1) ? A2 : A3);
        int c = 0;
        for (int m = 0; m < 21 && c < ANN; ++m) {
            float v = __ldg(A + n * 21 + m);
            if (v != 0.f) { Aw[(L*21+n)*ANN + c] = v; Ai[(L*21+n)*ANN + c] = (uint8_t)m; ++c; }
        }
        Acnt[L * 21 + n] = c;
    }
    if (tid < 192) Oac[tid] = 0.f;
    __syncthreads();

    float C[2][4][4];
    #define ZERO_C() { _Pragma("unroll") for (int mt=0;mt<2;++mt) _Pragma("unroll") \
        for (int j=0;j<4;++j) { C[mt][j][0]=0.f;C[mt][j][1]=0.f;C[mt][j][2]=0.f;C[mt][j][3]=0.f; } }

    // cooperative load of one 4-kstep unit (4 x 4 KB) into a slot
    auto ldBunit = [&](int fb, int fstride, int slot) {
        #pragma unroll
        for (int h = 0; h < 4; ++h) {
            const char* src = (const char*)&gWB[fb + h * fstride][0] + tid * 16;
            cp16(smB + (uint32_t)slot * 16384u + (uint32_t)h * 4096u + (uint32_t)tid * 16u, src);
        }
        CP_COMMIT();
    };

    // ---- pipelined sweep: 8 ksteps = 2 units of 4; 1 barrier per unit ----
    auto sweepK = [&](int fragbase, int fstride) {
        __syncthreads();                           // prev readers/writers of ring done
        ldBunit(fragbase, fstride, 0);
        #pragma unroll 1
        for (int u = 0; u < 2; ++u) {
            CP_WAIT(0);
            __syncthreads();
            if (u == 0) ldBunit(fragbase + 4 * fstride, fstride, 1);
            #pragma unroll
            for (int k4 = 0; k4 < 4; ++k4) {
                const int ks = u * 4 + k4;
                uint32_t ah[2][4], al[2][4];
                #pragma unroll
                for (int mt = 0; mt < 2; ++mt) {
                    uint32_t off = (uint32_t)(((arow + mt*16) * LDX + ks*16 + kadd) * 2);
                    LDSM_X4(ah[mt][0], ah[mt][1], ah[mt][2], ah[mt][3], xh + off);
                    LDSM_X4(al[mt][0], al[mt][1], al[mt][2], al[mt][3], xl + off);
                }
                const unsigned char* bp0 = sm + OFF_B + (u & 1) * 16384 + k4 * 4096
                                             + ng * 4 * 256 + lane * 8;
                #pragma unroll
                for (int j = 0; j < 4; ++j) {
                    uint2 b = *(const uint2*)(bp0 + j * 256);
                    #pragma unroll
                    for (int mt = 0; mt < 2; ++mt) {
                        MMA_F16(C[mt][j], ah[mt], b.x, b.y);
                        MMA_F16(C[mt][j], al[mt], b.x, b.y);
                    }
                }
            }
        }
    };

    // ---- layer-1 pre-mix: X_mixed = A1 @ x gathered from gmem, fp16 split ----
    auto premix_x = [&](int kc) {
        __syncthreads();
        #pragma unroll 1
        for (int idx = tid; idx < MROW * 32; idx += 256) {
            int r = idx >> 5, q = idx & 31;
            float4 s = make_float4(0.f, 0.f, 0.f, 0.f);
            if (r < rows_valid) {
                int n = rown[r];
                const int gbr = b0row + r - n;
                const int base = n * ANN, cnt = Acnt[n];
                for (int e = 0; e < cnt; ++e) {
                    float a = Aw[base + e];
                    const float4 v = __ldg((const float4*)(x + (size_t)(gbr + Ai[base+e]) * 256 + kc*128) + q);
                    s.x = fmaf(a, v.x, s.x); s.y = fmaf(a, v.y, s.y);
                    s.z = fmaf(a, v.z, s.z); s.w = fmaf(a, v.w, s.w);
                }
            }
            float h0 = __half2float(__float2half_rn(s.x));
            float h1 = __half2float(__float2half_rn(s.y));
            float h2 = __half2float(__float2half_rn(s.z));
            float h3 = __half2float(__float2half_rn(s.w));
            *(uint2*)(XH + r*LDX + q*4) = make_uint2(pack_h2(h0, h1), pack_h2(h2, h3));
            *(uint2*)(XL + r*LDX + q*4) =
                make_uint2(pack_h2(s.x - h0, s.y - h1), pack_h2(s.z - h2, s.w - h3));
        }
        __syncthreads();
    };

    // ---- layers 1/2 epilogue: C -> fp32 staging (ring overlay) -> vectorized
    //      A-mix (float4) fused with single hi/lo split-store ----
    auto epi12 = [&](const float* __restrict__ bias, int Lnext) {
        __syncthreads();                 // sweep done: ring free for staging
        #pragma unroll
        for (int mt = 0; mt < 2; ++mt)
            #pragma unroll
            for (int j = 0; j < 4; ++j) {
                int c  = ng*32 + j*8 + (lane&3)*2;
                float2 bb = __ldg((const float2*)(bias + c));
                int r0 = m0base + mt*16 + (lane>>2);
                *(float2*)(Xf + r0*LDF + c) = make_float2(
                    fmaxf(C[mt][j][0] + bb.x, 0.f), fmaxf(C[mt][j][1] + bb.y, 0.f));
                *(float2*)(Xf + (r0+8)*LDF + c) = make_float2(
                    fmaxf(C[mt][j][2] + bb.x, 0.f), fmaxf(C[mt][j][3] + bb.y, 0.f));
            }
        __syncthreads();
        #pragma unroll
        for (int t = 0; t < 8; ++t) {
            int idx = tid + t*256;
            int r = idx >> 5, c4 = (idx & 31) * 4;
            float4 s = make_float4(0.f, 0.f, 0.f, 0.f);
            if (r < rows_valid) {
                int n = rown[r], gb0 = r - n;
                int base = (Lnext*21 + n)*ANN, cnt = Acnt[Lnext*21 + n];
                for (int e = 0; e < cnt; ++e) {
                    float a = Aw[base + e];
                    const float4 v = *(const float4*)(Xf + (gb0 + Ai[base+e])*LDF + c4);
                    s.x = fmaf(a, v.x, s.x); s.y = fmaf(a, v.y, s.y);
                    s.z = fmaf(a, v.z, s.z); s.w = fmaf(a, v.w, s.w);
                }
            }
            float h0 = __half2float(__float2half_rn(s.x));
            float h1 = __half2float(__float2half_rn(s.y));
            float h2 = __half2float(__float2half_rn(s.z));
            float h3 = __half2float(__float2half_rn(s.w));
            *(uint2*)(XH + r*LDX + c4) = make_uint2(pack_h2(h0, h1), pack_h2(h2, h3));
            *(uint2*)(XL + r*LDX + c4) =
                make_uint2(pack_h2(s.x - h0, s.y - h1), pack_h2(s.z - h2, s.w - h3));
        }
        // no trailing barrier: next sweepK opens with one (covers XH/XL + ring reuse)
    };

    // ================= Layer 1: K=256 (2 pre-mixed chunks) =================
    ZERO_C();
    premix_x(0);
    sweepK(FR_W1,          16);
    premix_x(1);
    sweepK(FR_W1 + 8 * 16, 16);
    epi12(b1, 1);

    // ================= Layer 2: K=128 =================
    ZERO_C();
    sweepK(FR_W2, 16);
    epi12(b2, 2);

    // ================= Layer 3: K=128, N=512 (4 n-chunks), register epi =====
    #pragma unroll 1
    for (int nc = 0; nc < 4; ++nc) {
        ZERO_C();
        sweepK(FR_W3 + nc * 16, 64);
        float facc[12];
        #pragma unroll
        for (int i = 0; i < 12; ++i) facc[i] = 0.f;
        #pragma unroll
        for (int mt = 0; mt < 2; ++mt)
            #pragma unroll
            for (int j = 0; j < 4; ++j) {
                int cg = nc*128 + ng*32 + j*8 + (lane&3)*2;
                float2 bb = __ldg((const float2*)(b3 + cg));
                int r0 = m0base + mt*16 + (lane>>2);
                bool ok0 = (r0     < rows_valid);
                bool ok1 = (r0 + 8 < rows_valid);
                float v00 = ok0 ? fmaxf(C[mt][j][0] + bb.x, 0.f) : 0.f;
                float v01 = ok0 ? fmaxf(C[mt][j][1] + bb.y, 0.f) : 0.f;
                float v10 = ok1 ? fmaxf(C[mt][j][2] + bb.x, 0.f) : 0.f;
                float v11 = ok1 ? fmaxf(C[mt][j][3] + bb.y, 0.f) : 0.f;
                if (ok0) *(float2*)(x3g + (size_t)(b0row + r0    )*512 + cg) = make_float2(v00, v01);
                if (ok1) *(float2*)(x3g + (size_t)(b0row + r0 + 8)*512 + cg) = make_float2(v10, v11);
                #pragma unroll
                for (int jo = 0; jo < 3; ++jo) {
                    float w0 = __ldg(fcW + (size_t)cg*3 + jo);
                    float w1 = __ldg(fcW + (size_t)(cg+1)*3 + jo);
                    facc[(mt*2+0)*3 + jo] += v00*w0 + v01*w1;
                    facc[(mt*2+1)*3 + jo] += v10*w0 + v11*w1;
                }
            }
        #pragma unroll
        for (int i = 0; i < 12; ++i) {
            facc[i] += __shfl_xor_sync(0xFFFFFFFF, facc[i], 1);
            facc[i] += __shfl_xor_sync(0xFFFFFFFF, facc[i], 2);
        }
        if ((lane & 3) == 0) {
            #pragma unroll
            for (int mt = 0; mt < 2; ++mt)
                #pragma unroll
                for (int rh = 0; rh < 2; ++rh) {
                    int r = m0base + mt*16 + (lane>>2) + rh*8;
                    if (r < rows_valid) {
                        #pragma unroll
                        for (int jo = 0; jo < 3; ++jo)
                            atomicAdd(&Oac[r*3 + jo], facc[(mt*2+rh)*3 + jo]);
                    }
                }
        }
    }

    // ---- final out = FC + fcb ----
    __syncthreads();
    if (tid < 189) {
        int r = tid / 3, j = tid - 3*r;
        if (r < rows_valid)
            outg[(size_t)(b0row + r)*3 + j] = Oac[tid] + __ldg(fcb + j);
    }
    #undef ZERO_C
}

extern "C" void kernel_launch(void* const* d_in, const int* in_sizes, int n_in,
                              void* d_out, int out_size) {
    const float* x   = (const float*)d_in[0];
    const float* A1  = (const float*)d_in[1];
    const float* A2  = (const float*)d_in[2];
    const float* A3  = (const float*)d_in[3];
    const float* W1  = (const float*)d_in[4];
    const float* b1  = (const float*)d_in[5];
    const float* W2  = (const float*)d_in[6];
    const float* b2  = (const float*)d_in[7];
    const float* W3  = (const float*)d_in[8];
    const float* b3  = (const float*)d_in[9];
    const float* fcW = (const float*)d_in[10];
    const float* fcb = (const float*)d_in[11];

    const int Btot = in_sizes[0] / (21 * 256);
    float* x3g  = (float*)d_out;
    float* outg = x3g + (size_t)Btot * 21 * 512;

    static int attr_done = 0;
    if (!attr_done) {
        cudaFuncSetAttribute(handnet_mma, cudaFuncAttributeMaxDynamicSharedMemorySize, SMEM_SZ);
        attr_done = 1;
    }

    prep_frags<<<NFRAG, 32>>>(W1, W2, W3);
    const int nCTA = (Btot * 21 + RPC - 1) / RPC;
    handnet_mma<<<nCTA, 256, SMEM_SZ>>>(x, A1, A2, A3, b1, b2, b3, fcW, fcb,
                                        x3g, outg, Btot);
}

// round 12
// speedup vs baseline: 1.6890x; 1.6890x over previous
#include <cuda_runtime.h>
#include <cuda_fp16.h>
#include <cstdint>

// ============================================================
// Portable-PTX (base sm_103): ldmatrix + mma.sync fp16, single-pass
// (A and B both RN-rounded fp16; fp32 accum). 4 CTAs/SM, M=64/CTA,
// cp.async B pipeline (4-kstep units, 1 barrier/unit)
// ============================================================
__device__ __forceinline__ uint32_t smem_u32(const void* p) {
    uint32_t a;
    asm("{ .reg .u64 t; cvta.to.shared.u64 t, %1; cvt.u32.u64 %0, t; }" : "=r"(a) : "l"(p));
    return a;
}
#define LDSM_X4(a0,a1,a2,a3,addr) \
    asm volatile("ldmatrix.sync.aligned.m8n8.x4.shared.b16 {%0,%1,%2,%3}, [%4];" \
        : "=r"(a0), "=r"(a1), "=r"(a2), "=r"(a3) : "r"(addr))
#define MMA_F16(c, a, b0, b1) \
    asm volatile("mma.sync.aligned.m16n8k16.row.col.f32.f16.f16.f32 " \
        "{%0,%1,%2,%3}, {%4,%5,%6,%7}, {%8,%9}, {%0,%1,%2,%3};" \
        : "+f"((c)[0]), "+f"((c)[1]), "+f"((c)[2]), "+f"((c)[3]) \
        : "r"((a)[0]), "r"((a)[1]), "r"((a)[2]), "r"((a)[3]), "r"(b0), "r"(b1))
__device__ __forceinline__ void cp16(uint32_t dst, const void* src) {
    asm volatile("cp.async.ca.shared.global [%0], [%1], 16;" :: "r"(dst), "l"(src));
}
#define CP_COMMIT()  asm volatile("cp.async.commit_group;" ::: "memory")
#define CP_WAIT(n)   asm volatile("cp.async.wait_group %0;" :: "n"(n) : "memory")

namespace {
constexpr int LDX  = 136;   // fp16 row stride (272 B -> LDSM conflict-free)
constexpr int ANN  = 12;    // max nnz per A row
constexpr int MROW = 64;    // rows per CTA tile (63 valid = 3 batches)
constexpr int RPC  = 63;
// dynamic smem offsets
constexpr int OFF_XH   = 0;            // [64][136] fp16 = 17408
constexpr int OFF_B    = 17408;        // ring 2 x 16384 = 32768
constexpr int OFF_AW   = 50176;        // [3][21][12] f32 = 3024
constexpr int OFF_AI   = 53200;        // [3][21][12] u8  = 768
constexpr int OFF_ACNT = 53968;        // i32[64]  = 256
constexpr int OFF_OAC  = 54224;        // f32[192] = 768
constexpr int OFF_ROWN = 54992;        // u8[64]
constexpr int SMEM_SZ  = 55296;        // x4 CTAs = 216 KB < 227 KB
// fragment bases (1 frag = B for one (kstep, n-tile); 256 B = 32 lanes x 8 B)
constexpr int FR_W1 = 0;      // 16 ks * 16 nt = 256
constexpr int FR_W2 = 256;    //  8 ks * 16 nt = 128
constexpr int FR_W3 = 384;    //  8 ks * 64 nt = 512
constexpr int NFRAG = 896;
} // namespace

// Per-lane B fragments (fp16x2 pairs). 16 consecutive frags (one CTA k-step)
// = 4 KB contiguous -> bulk cp.async. L2-resident.
__device__ __align__(16) uint2 gWB[NFRAG][32];

__device__ __forceinline__ uint32_t pack_h2(float x, float y) {
    __half2 h = __floats2half2_rn(x, y);
    return *reinterpret_cast<uint32_t*>(&h);
}

// frag id = base + ks*NT + nt
__global__ void prep_frags(const float* __restrict__ W1,
                           const float* __restrict__ W2,
                           const float* __restrict__ W3) {
    const int id = blockIdx.x, l = threadIdx.x;
    const float* W; int ld, r, NT;
    if (id < 256)      { W = W1; ld = 128; r = id;       NT = 16; }
    else if (id < 384) { W = W2; ld = 128; r = id - 256; NT = 16; }
    else               { W = W3; ld = 512; r = id - 384; NT = 64; }
    const int nt = r % NT, ks = r / NT;
    const int n  = nt * 8 + (l >> 2);
    const int k0 = ks * 16 + (l & 3) * 2;
    float v[4];
    #pragma unroll
    for (int i = 0; i < 4; ++i)
        v[i] = W[(size_t)(k0 + (i >> 1) * 8 + (i & 1)) * ld + n];
    gWB[id][l] = make_uint2(pack_h2(v[0], v[1]), pack_h2(v[2], v[3]));
}

__global__ void __launch_bounds__(256, 4)
handnet_mma(const float* __restrict__ x,
            const float* __restrict__ A1, const float* __restrict__ A2,
            const float* __restrict__ A3,
            const float* __restrict__ b1, const float* __restrict__ b2,
            const float* __restrict__ b3,
            const float* __restrict__ fcW, const float* __restrict__ fcb,
            float* __restrict__ x3g, float* __restrict__ outg, int Btot)
{
    extern __shared__ unsigned char sm[];
    __half*  XH   = (__half*)(sm + OFF_XH);
    float*   Aw   = (float*)(sm + OFF_AW);
    uint8_t* Ai   = sm + OFF_AI;
    int*     Acnt = (int*)(sm + OFF_ACNT);
    float*   Oac  = (float*)(sm + OFF_OAC);
    uint8_t* rown = sm + OFF_ROWN;

    const int tid = threadIdx.x, lane = tid & 31, wid = tid >> 5;
    const int mg = wid >> 2, ng = wid & 3;        // 2 m-groups x 4 n-groups
    const int m0base = mg * 32;
    const int arow = m0base + (lane & 7) + ((lane >> 3) & 1) * 8;
    const int kadd = ((lane >> 4) & 1) * 8;
    const uint32_t xh = smem_u32(XH);
    const uint32_t smB = smem_u32(sm + OFF_B);

    const int b0row = blockIdx.x * RPC;
    const int rows_valid = min(RPC, Btot * 21 - b0row);

    // ---- setup ----
    if (tid < MROW) rown[tid] = (uint8_t)(tid % 21);
    if (tid < 63) {
        int L = tid / 21, n = tid % 21;
        const float* A = (L == 0) ? A1 : ((L == 1) ? A2 : A3);
        int c = 0;
        for (int m = 0; m < 21 && c < ANN; ++m) {
            float v = __ldg(A + n * 21 + m);
            if (v != 0.f) { Aw[(L*21+n)*ANN + c] = v; Ai[(L*21+n)*ANN + c] = (uint8_t)m; ++c; }
        }
        Acnt[L * 21 + n] = c;
    }
    if (tid < 192) Oac[tid] = 0.f;
    __syncthreads();

    float C[2][4][4];
    #define ZERO_C() { _Pragma("unroll") for (int mt=0;mt<2;++mt) _Pragma("unroll") \
        for (int j=0;j<4;++j) { C[mt][j][0]=0.f;C[mt][j][1]=0.f;C[mt][j][2]=0.f;C[mt][j][3]=0.f; } }

    // cooperative load of one 4-kstep unit (4 x 4 KB) into a slot
    auto ldBunit = [&](int fb, int fstride, int slot) {
        #pragma unroll
        for (int h = 0; h < 4; ++h) {
            const char* src = (const char*)&gWB[fb + h * fstride][0] + tid * 16;
            cp16(smB + (uint32_t)slot * 16384u + (uint32_t)h * 4096u + (uint32_t)tid * 16u, src);
        }
        CP_COMMIT();
    };

    // ---- pipelined single-pass sweep: 8 ksteps = 2 units; 1 barrier/unit ----
    auto sweepK = [&](int fragbase, int fstride) {
        __syncthreads();                           // prev readers of ring done
        ldBunit(fragbase, fstride, 0);
        #pragma unroll 1
        for (int u = 0; u < 2; ++u) {
            CP_WAIT(0);
            __syncthreads();
            if (u == 0) ldBunit(fragbase + 4 * fstride, fstride, 1);
            #pragma unroll
            for (int k4 = 0; k4 < 4; ++k4) {
                const int ks = u * 4 + k4;
                uint32_t ah[2][4];
                #pragma unroll
                for (int mt = 0; mt < 2; ++mt) {
                    uint32_t off = (uint32_t)(((arow + mt*16) * LDX + ks*16 + kadd) * 2);
                    LDSM_X4(ah[mt][0], ah[mt][1], ah[mt][2], ah[mt][3], xh + off);
                }
                const unsigned char* bp0 = sm + OFF_B + (u & 1) * 16384 + k4 * 4096
                                             + ng * 4 * 256 + lane * 8;
                #pragma unroll
                for (int j = 0; j < 4; ++j) {
                    uint2 b = *(const uint2*)(bp0 + j * 256);
                    MMA_F16(C[0][j], ah[0], b.x, b.y);
                    MMA_F16(C[1][j], ah[1], b.x, b.y);
                }
            }
        }
    };

    // ---- layer-1 pre-mix: X_mixed = A1 @ x gathered from gmem -> fp16 ----
    auto premix_x = [&](int kc) {
        __syncthreads();
        #pragma unroll 1
        for (int idx = tid; idx < MROW * 32; idx += 256) {
            int r = idx >> 5, q = idx & 31;
            float4 s = make_float4(0.f, 0.f, 0.f, 0.f);
            if (r < rows_valid) {
                int n = rown[r];
                const int gbr = b0row + r - n;
                const int base = n * ANN, cnt = Acnt[n];
                for (int e = 0; e < cnt; ++e) {
                    float a = Aw[base + e];
                    const float4 v = __ldg((const float4*)(x + (size_t)(gbr + Ai[base+e]) * 256 + kc*128) + q);
                    s.x = fmaf(a, v.x, s.x); s.y = fmaf(a, v.y, s.y);
                    s.z = fmaf(a, v.z, s.z); s.w = fmaf(a, v.w, s.w);
                }
            }
            *(uint2*)(XH + r*LDX + q*4) = make_uint2(pack_h2(s.x, s.y), pack_h2(s.z, s.w));
        }
        __syncthreads();
    };

    // ---- layers 1/2 epilogue: bias+relu -> XH, then chunk-paced in-place
    //      A-mix on half2 pairs (4 chunks of 32 cols, barrier-paced) ----
    auto epi12 = [&](const float* __restrict__ bias, int Lnext) {
        __syncthreads();
        #pragma unroll
        for (int mt = 0; mt < 2; ++mt)
            #pragma unroll
            for (int j = 0; j < 4; ++j) {
                int c  = ng*32 + j*8 + (lane&3)*2;
                float2 bb = __ldg((const float2*)(bias + c));
                int r0 = m0base + mt*16 + (lane>>2);
                *(uint32_t*)(XH + r0*LDX + c) =
                    pack_h2(fmaxf(C[mt][j][0] + bb.x, 0.f), fmaxf(C[mt][j][1] + bb.y, 0.f));
                *(uint32_t*)(XH + (r0+8)*LDX + c) =
                    pack_h2(fmaxf(C[mt][j][2] + bb.x, 0.f), fmaxf(C[mt][j][3] + bb.y, 0.f));
            }
        __syncthreads();
        #pragma unroll 1
        for (int ch = 0; ch < 4; ++ch) {
            float2 mv[4];
            #pragma unroll
            for (int t = 0; t < 4; ++t) {
                int idx = tid + t*256;
                int r = idx >> 4, c = ch*32 + (idx & 15)*2;
                float2 s = make_float2(0.f, 0.f);
                if (r < rows_valid) {
                    int n = rown[r], gb0 = r - n;
                    int base = (Lnext*21 + n)*ANN, cnt = Acnt[Lnext*21 + n];
                    for (int e = 0; e < cnt; ++e) {
                        float a = Aw[base + e];
                        __half2 hv = *(const __half2*)(XH + (gb0 + Ai[base+e])*LDX + c);
                        float2 v = __half22float2(hv);
                        s.x = fmaf(a, v.x, s.x);
                        s.y = fmaf(a, v.y, s.y);
                    }
                }
                mv[t] = s;
            }
            __syncthreads();
            #pragma unroll
            for (int t = 0; t < 4; ++t) {
                int idx = tid + t*256;
                int r = idx >> 4, c = ch*32 + (idx & 15)*2;
                *(uint32_t*)(XH + r*LDX + c) = pack_h2(mv[t].x, mv[t].y);
            }
            __syncthreads();
        }
    };

    // ================= Layer 1: K=256 (2 pre-mixed chunks) =================
    ZERO_C();
    premix_x(0);
    sweepK(FR_W1,          16);
    premix_x(1);
    sweepK(FR_W1 + 8 * 16, 16);
    epi12(b1, 1);

    // ================= Layer 2: K=128 =================
    ZERO_C();
    sweepK(FR_W2, 16);
    epi12(b2, 2);

    // ================= Layer 3: K=128, N=512 (4 n-chunks), register epi =====
    #pragma unroll 1
    for (int nc = 0; nc < 4; ++nc) {
        ZERO_C();
        sweepK(FR_W3 + nc * 16, 64);
        float facc[12];
        #pragma unroll
        for (int i = 0; i < 12; ++i) facc[i] = 0.f;
        #pragma unroll
        for (int mt = 0; mt < 2; ++mt)
            #pragma unroll
            for (int j = 0; j < 4; ++j) {
                int cg = nc*128 + ng*32 + j*8 + (lane&3)*2;
                float2 bb = __ldg((const float2*)(b3 + cg));
                int r0 = m0base + mt*16 + (lane>>2);
                bool ok0 = (r0     < rows_valid);
                bool ok1 = (r0 + 8 < rows_valid);
                float v00 = ok0 ? fmaxf(C[mt][j][0] + bb.x, 0.f) : 0.f;
                float v01 = ok0 ? fmaxf(C[mt][j][1] + bb.y, 0.f) : 0.f;
                float v10 = ok1 ? fmaxf(C[mt][j][2] + bb.x, 0.f) : 0.f;
                float v11 = ok1 ? fmaxf(C[mt][j][3] + bb.y, 0.f) : 0.f;
                if (ok0) *(float2*)(x3g + (size_t)(b0row + r0    )*512 + cg) = make_float2(v00, v01);
                if (ok1) *(float2*)(x3g + (size_t)(b0row + r0 + 8)*512 + cg) = make_float2(v10, v11);
                #pragma unroll
                for (int jo = 0; jo < 3; ++jo) {
                    float w0 = __ldg(fcW + (size_t)cg*3 + jo);
                    float w1 = __ldg(fcW + (size_t)(cg+1)*3 + jo);
                    facc[(mt*2+0)*3 + jo] += v00*w0 + v01*w1;
                    facc[(mt*2+1)*3 + jo] += v10*w0 + v11*w1;
                }
            }
        #pragma unroll
        for (int i = 0; i < 12; ++i) {
            facc[i] += __shfl_xor_sync(0xFFFFFFFF, facc[i], 1);
            facc[i] += __shfl_xor_sync(0xFFFFFFFF, facc[i], 2);
        }
        if ((lane & 3) == 0) {
            #pragma unroll
            for (int mt = 0; mt < 2; ++mt)
                #pragma unroll
                for (int rh = 0; rh < 2; ++rh) {
                    int r = m0base + mt*16 + (lane>>2) + rh*8;
                    if (r < rows_valid) {
                        #pragma unroll
                        for (int jo = 0; jo < 3; ++jo)
                            atomicAdd(&Oac[r*3 + jo], facc[(mt*2+rh)*3 + jo]);
                    }
                }
        }
    }

    // ---- final out = FC + fcb ----
    __syncthreads();
    if (tid < 189) {
        int r = tid / 3, j = tid - 3*r;
        if (r < rows_valid)
            outg[(size_t)(b0row + r)*3 + j] = Oac[tid] + __ldg(fcb + j);
    }
    #undef ZERO_C
}

extern "C" void kernel_launch(void* const* d_in, const int* in_sizes, int n_in,
                              void* d_out, int out_size) {
    const float* x   = (const float*)d_in[0];
    const float* A1  = (const float*)d_in[1];
    const float* A2  = (const float*)d_in[2];
    const float* A3  = (const float*)d_in[3];
    const float* W1  = (const float*)d_in[4];
    const float* b1  = (const float*)d_in[5];
    const float* W2  = (const float*)d_in[6];
    const float* b2  = (const float*)d_in[7];
    const float* W3  = (const float*)d_in[8];
    const float* b3  = (const float*)d_in[9];
    const float* fcW = (const float*)d_in[10];
    const float* fcb = (const float*)d_in[11];

    const int Btot = in_sizes[0] / (21 * 256);
    float* x3g  = (float*)d_out;
    float* outg = x3g + (size_t)Btot * 21 * 512;

    static int attr_done = 0;
    if (!attr_done) {
        cudaFuncSetAttribute(handnet_mma, cudaFuncAttributeMaxDynamicSharedMemorySize, SMEM_SZ);
        attr_done = 1;
    }

    prep_frags<<<NFRAG, 32>>>(W1, W2, W3);
    const int nCTA = (Btot * 21 + RPC - 1) / RPC;
    handnet_mma<<<nCTA, 256, SMEM_SZ>>>(x, A1, A2, A3, b1, b2, b3, fcW, fcb,
                                        x3g, outg, Btot);
}

// round 13
// speedup vs baseline: 2.0246x; 1.1987x over previous
#include <cuda_runtime.h>
#include <cuda_fp16.h>
#include <cstdint>

// ============================================================
// Portable-PTX (base sm_103): ldmatrix + mma.sync fp16, single-pass.
// 4 CTAs/SM, M=64/CTA, cp.async B pipeline (4-kstep units).
// A-mix (graph aggregation) ALSO on tensor cores: Y = P @ X with
// P = block-diag 0/1 adjacency (exact in fp16).
// ============================================================
__device__ __forceinline__ uint32_t smem_u32(const void* p) {
    uint32_t a;
    asm("{ .reg .u64 t; cvta.to.shared.u64 t, %1; cvt.u32.u64 %0, t; }" : "=r"(a) : "l"(p));
    return a;
}
#define LDSM_X4(a0,a1,a2,a3,addr) \
    asm volatile("ldmatrix.sync.aligned.m8n8.x4.shared.b16 {%0,%1,%2,%3}, [%4];" \
        : "=r"(a0), "=r"(a1), "=r"(a2), "=r"(a3) : "r"(addr))
#define LDSM_X4_T(a0,a1,a2,a3,addr) \
    asm volatile("ldmatrix.sync.aligned.m8n8.x4.trans.shared.b16 {%0,%1,%2,%3}, [%4];" \
        : "=r"(a0), "=r"(a1), "=r"(a2), "=r"(a3) : "r"(addr))
#define MMA_F16(c, a, b0, b1) \
    asm volatile("mma.sync.aligned.m16n8k16.row.col.f32.f16.f16.f32 " \
        "{%0,%1,%2,%3}, {%4,%5,%6,%7}, {%8,%9}, {%0,%1,%2,%3};" \
        : "+f"((c)[0]), "+f"((c)[1]), "+f"((c)[2]), "+f"((c)[3]) \
        : "r"((a)[0]), "r"((a)[1]), "r"((a)[2]), "r"((a)[3]), "r"(b0), "r"(b1))
__device__ __forceinline__ void cp16(uint32_t dst, const void* src) {
    asm volatile("cp.async.ca.shared.global [%0], [%1], 16;" :: "r"(dst), "l"(src));
}
#define CP_COMMIT()  asm volatile("cp.async.commit_group;" ::: "memory")
#define CP_WAIT(n)   asm volatile("cp.async.wait_group %0;" :: "n"(n) : "memory")

namespace {
constexpr int LDX  = 136;   // fp16 row stride (272 B -> LDSM conflict-free)
constexpr int ANN  = 12;    // max nnz per A row (layer-1 gmem premix)
constexpr int MROW = 64;    // rows per CTA tile (63 valid = 3 batches)
constexpr int RPC  = 63;
// dynamic smem offsets
constexpr int OFF_XH   = 0;            // [64][136] fp16 = 17408
constexpr int OFF_B    = 17408;        // ring 2 x 16384 = 32768
constexpr int OFF_AW   = 50176;        // [21][12] f32 (A1 only) = 1008 (pad 3024)
constexpr int OFF_AI   = 53200;        // [21][12] u8 = 768
constexpr int OFF_ACNT = 53968;        // i32[64] = 256
constexpr int OFF_OAC  = 54224;        // f32[192] = 768
constexpr int OFF_ROWN = 54992;        // u8[64]
constexpr int SMEM_SZ  = 55296;        // x4 CTAs = 216 KB
// fragment bases (1 frag = B for one (kstep, n-tile); 256 B)
constexpr int FR_W1 = 0;      // 16 ks * 16 nt = 256
constexpr int FR_W2 = 256;    //  8 ks * 16 nt = 128
constexpr int FR_W3 = 384;    //  8 ks * 64 nt = 512
constexpr int NFRAG = 896;
constexpr int NPREP = NFRAG + 48;   // + 3L x 4mtile x 4ks P-fragment builders
} // namespace

// Per-lane B fragments (fp16x2). 16 consecutive frags (one CTA k-step) = 4 KB.
__device__ __align__(16) uint2 gWB[NFRAG][32];
// P (mix matrix) A-operand fragments: [L][mtile][ks][lane] (exact 0/1 fp16).
__device__ __align__(16) uint4 gP[3][4][4][32];

__device__ __forceinline__ uint32_t pack_h2(float x, float y) {
    __half2 h = __floats2half2_rn(x, y);
    return *reinterpret_cast<uint32_t*>(&h);
}

__global__ void prep_frags(const float* __restrict__ W1,
                           const float* __restrict__ W2,
                           const float* __restrict__ W3,
                           const float* __restrict__ A1,
                           const float* __restrict__ A2,
                           const float* __restrict__ A3) {
    const int id = blockIdx.x, l = threadIdx.x;
    if (id < NFRAG) {
        const float* W; int ld, r, NT;
        if (id < 256)      { W = W1; ld = 128; r = id;       NT = 16; }
        else if (id < 384) { W = W2; ld = 128; r = id - 256; NT = 16; }
        else               { W = W3; ld = 512; r = id - 384; NT = 64; }
        const int nt = r % NT, ks = r / NT;
        const int n  = nt * 8 + (l >> 2);
        const int k0 = ks * 16 + (l & 3) * 2;
        float v[4];
        #pragma unroll
        for (int i = 0; i < 4; ++i)
            v[i] = W[(size_t)(k0 + (i >> 1) * 8 + (i & 1)) * ld + n];
        gWB[id][l] = make_uint2(pack_h2(v[0], v[1]), pack_h2(v[2], v[3]));
    } else {
        // P fragments: block-diag mix matrix, m16k16 A-operand layout.
        int id2 = id - NFRAG;
        int L = id2 >> 4, mtile = (id2 >> 2) & 3, ks = id2 & 3;
        const float* A = (L == 0) ? A1 : ((L == 1) ? A2 : A3);
        const int r0 = mtile * 16 + (l >> 2);
        const int c0 = ks * 16 + (l & 3) * 2;
        float v[8];   // a0:{r0,c0..c0+1} a1:{r0+8} a2:{r0,c0+8..9} a3:{r0+8,c0+8..9}
        #pragma unroll
        for (int i = 0; i < 8; ++i) {
            int rr = r0 + ((i >> 1) & 1) * 8;
            int cc = c0 + (i & 1) + (i >> 2) * 8;
            float p = 0.f;
            if (rr < 63 && cc < 63 && (rr / 21) == (cc / 21))
                p = A[(rr % 21) * 21 + (cc % 21)];
            v[i] = p;
        }
        gP[L][mtile][ks][l] = make_uint4(pack_h2(v[0], v[1]), pack_h2(v[2], v[3]),
                                         pack_h2(v[4], v[5]), pack_h2(v[6], v[7]));
    }
}

__global__ void __launch_bounds__(256, 4)
handnet_mma(const float* __restrict__ x,
            const float* __restrict__ A1,
            const float* __restrict__ b1, const float* __restrict__ b2,
            const float* __restrict__ b3,
            const float* __restrict__ fcW, const float* __restrict__ fcb,
            float* __restrict__ x3g, float* __restrict__ outg, int Btot)
{
    extern __shared__ unsigned char sm[];
    __half*  XH   = (__half*)(sm + OFF_XH);
    float*   Aw   = (float*)(sm + OFF_AW);
    uint8_t* Ai   = sm + OFF_AI;
    int*     Acnt = (int*)(sm + OFF_ACNT);
    float*   Oac  = (float*)(sm + OFF_OAC);
    uint8_t* rown = sm + OFF_ROWN;

    const int tid = threadIdx.x, lane = tid & 31, wid = tid >> 5;
    const int mg = wid >> 2, ng = wid & 3;        // 2 m-groups x 4 n-groups
    const int m0base = mg * 32;
    const int arow = m0base + (lane & 7) + ((lane >> 3) & 1) * 8;
    const int kadd = ((lane >> 4) & 1) * 8;
    const uint32_t xh = smem_u32(XH);
    const uint32_t smB = smem_u32(sm + OFF_B);
    // trans-LDSM address components for mix B loads (lane-fixed)
    const int tmi = lane >> 3, trow = lane & 7;

    const int b0row = blockIdx.x * RPC;
    const int rows_valid = min(RPC, Btot * 21 - b0row);

    // ---- setup: A1 sparse lists (layer-1 gmem premix only) ----
    if (tid < MROW) rown[tid] = (uint8_t)(tid % 21);
    if (tid < 21) {
        int n = tid, c = 0;
        for (int m = 0; m < 21 && c < ANN; ++m) {
            float v = __ldg(A1 + n * 21 + m);
            if (v != 0.f) { Aw[n*ANN + c] = v; Ai[n*ANN + c] = (uint8_t)m; ++c; }
        }
        Acnt[n] = c;
    }
    if (tid < 192) Oac[tid] = 0.f;
    __syncthreads();

    float C[2][4][4];
    #define ZERO_C() { _Pragma("unroll") for (int mt=0;mt<2;++mt) _Pragma("unroll") \
        for (int j=0;j<4;++j) { C[mt][j][0]=0.f;C[mt][j][1]=0.f;C[mt][j][2]=0.f;C[mt][j][3]=0.f; } }

    auto ldBunit = [&](int fb, int fstride, int slot) {
        #pragma unroll
        for (int h = 0; h < 4; ++h) {
            const char* src = (const char*)&gWB[fb + h * fstride][0] + tid * 16;
            cp16(smB + (uint32_t)slot * 16384u + (uint32_t)h * 4096u + (uint32_t)tid * 16u, src);
        }
        CP_COMMIT();
    };

    // ---- pipelined single-pass sweep: 8 ksteps = 2 units; 1 barrier/unit ----
    auto sweepK = [&](int fragbase, int fstride) {
        __syncthreads();
        ldBunit(fragbase, fstride, 0);
        #pragma unroll 1
        for (int u = 0; u < 2; ++u) {
            CP_WAIT(0);
            __syncthreads();
            if (u == 0) ldBunit(fragbase + 4 * fstride, fstride, 1);
            #pragma unroll
            for (int k4 = 0; k4 < 4; ++k4) {
                const int ks = u * 4 + k4;
                uint32_t ah[2][4];
                #pragma unroll
                for (int mt = 0; mt < 2; ++mt) {
                    uint32_t off = (uint32_t)(((arow + mt*16) * LDX + ks*16 + kadd) * 2);
                    LDSM_X4(ah[mt][0], ah[mt][1], ah[mt][2], ah[mt][3], xh + off);
                }
                const unsigned char* bp0 = sm + OFF_B + (u & 1) * 16384 + k4 * 4096
                                             + ng * 4 * 256 + lane * 8;
                #pragma unroll
                for (int j = 0; j < 4; ++j) {
                    uint2 b = *(const uint2*)(bp0 + j * 256);
                    MMA_F16(C[0][j], ah[0], b.x, b.y);
                    MMA_F16(C[1][j], ah[1], b.x, b.y);
                }
            }
        }
    };

    // ---- layer-1 pre-mix: X_mixed = A1 @ x gathered from gmem -> fp16 ----
    auto premix_x = [&](int kc) {
        __syncthreads();
        #pragma unroll 1
        for (int idx = tid; idx < MROW * 32; idx += 256) {
            int r = idx >> 5, q = idx & 31;
            float4 s = make_float4(0.f, 0.f, 0.f, 0.f);
            if (r < rows_valid) {
                int n = rown[r];
                const int gbr = b0row + r - n;
                const int base = n * ANN, cnt = Acnt[n];
                for (int e = 0; e < cnt; ++e) {
                    float a = Aw[base + e];
                    const float4 v = __ldg((const float4*)(x + (size_t)(gbr + Ai[base+e]) * 256 + kc*128) + q);
                    s.x = fmaf(a, v.x, s.x); s.y = fmaf(a, v.y, s.y);
                    s.z = fmaf(a, v.z, s.z); s.w = fmaf(a, v.w, s.w);
                }
            }
            *(uint2*)(XH + r*LDX + q*4) = make_uint2(pack_h2(s.x, s.y), pack_h2(s.z, s.w));
        }
        __syncthreads();
    };

    // ---- layers 1/2 epilogue: bias+relu -> XH; then tensor-core mix
    //      Y = P @ X  (P block-diag 0/1 fragments from gP, X via trans-LDSM) ----
    auto epi12 = [&](const float* __restrict__ bias, int Lnext) {
        __syncthreads();
        #pragma unroll
        for (int mt = 0; mt < 2; ++mt)
            #pragma unroll
            for (int j = 0; j < 4; ++j) {
                int c  = ng*32 + j*8 + (lane&3)*2;
                float2 bb = __ldg((const float2*)(bias + c));
                int r0 = m0base + mt*16 + (lane>>2);
                *(uint32_t*)(XH + r0*LDX + c) =
                    pack_h2(fmaxf(C[mt][j][0] + bb.x, 0.f), fmaxf(C[mt][j][1] + bb.y, 0.f));
                *(uint32_t*)(XH + (r0+8)*LDX + c) =
                    pack_h2(fmaxf(C[mt][j][2] + bb.x, 0.f), fmaxf(C[mt][j][3] + bb.y, 0.f));
            }
        __syncthreads();
        ZERO_C();
        #pragma unroll
        for (int ks = 0; ks < 4; ++ks) {
            // X as B-operand: row-major [k][n] via trans ldmatrix, 2 chunks of n16
            uint32_t bt[2][4];
            #pragma unroll
            for (int ch = 0; ch < 2; ++ch) {
                uint32_t off = (uint32_t)(((ks*16 + (tmi&1)*8 + trow) * LDX
                                 + ng*32 + ch*16 + (tmi>>1)*8) * 2);
                LDSM_X4_T(bt[ch][0], bt[ch][1], bt[ch][2], bt[ch][3], xh + off);
            }
            #pragma unroll
            for (int mt = 0; mt < 2; ++mt) {
                uint4 p4 = __ldg(&gP[Lnext][mg*2 + mt][ks][lane]);
                uint32_t ap[4] = {p4.x, p4.y, p4.z, p4.w};
                MMA_F16(C[mt][0], ap, bt[0][0], bt[0][1]);
                MMA_F16(C[mt][1], ap, bt[0][2], bt[0][3]);
                MMA_F16(C[mt][2], ap, bt[1][0], bt[1][1]);
                MMA_F16(C[mt][3], ap, bt[1][2], bt[1][3]);
            }
        }
        __syncthreads();   // all XH reads complete before overwrite
        #pragma unroll
        for (int mt = 0; mt < 2; ++mt)
            #pragma unroll
            for (int j = 0; j < 4; ++j) {
                int c  = ng*32 + j*8 + (lane&3)*2;
                int r0 = m0base + mt*16 + (lane>>2);
                *(uint32_t*)(XH + r0*LDX + c)     = pack_h2(C[mt][j][0], C[mt][j][1]);
                *(uint32_t*)(XH + (r0+8)*LDX + c) = pack_h2(C[mt][j][2], C[mt][j][3]);
            }
        // next sweepK opens with a barrier
    };

    // ================= Layer 1: K=256 (2 pre-mixed chunks) =================
    ZERO_C();
    premix_x(0);
    sweepK(FR_W1,          16);
    premix_x(1);
    sweepK(FR_W1 + 8 * 16, 16);
    epi12(b1, 1);

    // ================= Layer 2: K=128 =================
    ZERO_C();
    sweepK(FR_W2, 16);
    epi12(b2, 2);

    // ================= Layer 3: K=128, N=512 (4 n-chunks), register epi =====
    #pragma unroll 1
    for (int nc = 0; nc < 4; ++nc) {
        ZERO_C();
        sweepK(FR_W3 + nc * 16, 64);
        float facc[12];
        #pragma unroll
        for (int i = 0; i < 12; ++i) facc[i] = 0.f;
        #pragma unroll
        for (int mt = 0; mt < 2; ++mt)
            #pragma unroll
            for (int j = 0; j < 4; ++j) {
                int cg = nc*128 + ng*32 + j*8 + (lane&3)*2;
                float2 bb = __ldg((const float2*)(b3 + cg));
                int r0 = m0base + mt*16 + (lane>>2);
                bool ok0 = (r0     < rows_valid);
                bool ok1 = (r0 + 8 < rows_valid);
                float v00 = ok0 ? fmaxf(C[mt][j][0] + bb.x, 0.f) : 0.f;
                float v01 = ok0 ? fmaxf(C[mt][j][1] + bb.y, 0.f) : 0.f;
                float v10 = ok1 ? fmaxf(C[mt][j][2] + bb.x, 0.f) : 0.f;
                float v11 = ok1 ? fmaxf(C[mt][j][3] + bb.y, 0.f) : 0.f;
                if (ok0) *(float2*)(x3g + (size_t)(b0row + r0    )*512 + cg) = make_float2(v00, v01);
                if (ok1) *(float2*)(x3g + (size_t)(b0row + r0 + 8)*512 + cg) = make_float2(v10, v11);
                #pragma unroll
                for (int jo = 0; jo < 3; ++jo) {
                    float w0 = __ldg(fcW + (size_t)cg*3 + jo);
                    float w1 = __ldg(fcW + (size_t)(cg+1)*3 + jo);
                    facc[(mt*2+0)*3 + jo] += v00*w0 + v01*w1;
                    facc[(mt*2+1)*3 + jo] += v10*w0 + v11*w1;
                }
            }
        #pragma unroll
        for (int i = 0; i < 12; ++i) {
            facc[i] += __shfl_xor_sync(0xFFFFFFFF, facc[i], 1);
            facc[i] += __shfl_xor_sync(0xFFFFFFFF, facc[i], 2);
        }
        if ((lane & 3) == 0) {
            #pragma unroll
            for (int mt = 0; mt < 2; ++mt)
                #pragma unroll
                for (int rh = 0; rh < 2; ++rh) {
                    int r = m0base + mt*16 + (lane>>2) + rh*8;
                    if (r < rows_valid) {
                        #pragma unroll
                        for (int jo = 0; jo < 3; ++jo)
                            atomicAdd(&Oac[r*3 + jo], facc[(mt*2+rh)*3 + jo]);
                    }
                }
        }
    }

    // ---- final out = FC + fcb ----
    __syncthreads();
    if (tid < 189) {
        int r = tid / 3, j = tid - 3*r;
        if (r < rows_valid)
            outg[(size_t)(b0row + r)*3 + j] = Oac[tid] + __ldg(fcb + j);
    }
    #undef ZERO_C
}

extern "C" void kernel_launch(void* const* d_in, const int* in_sizes, int n_in,
                              void* d_out, int out_size) {
    const float* x   = (const float*)d_in[0];
    const float* A1  = (const float*)d_in[1];
    const float* A2  = (const float*)d_in[2];
    const float* A3  = (const float*)d_in[3];
    const float* W1  = (const float*)d_in[4];
    const float* b1  = (const float*)d_in[5];
    const float* W2  = (const float*)d_in[6];
    const float* b2  = (const float*)d_in[7];
    const float* W3  = (const float*)d_in[8];
    const float* b3  = (const float*)d_in[9];
    const float* fcW = (const float*)d_in[10];
    const float* fcb = (const float*)d_in[11];

    const int Btot = in_sizes[0] / (21 * 256);
    float* x3g  = (float*)d_out;
    float* outg = x3g + (size_t)Btot * 21 * 512;

    static int attr_done = 0;
    if (!attr_done) {
        cudaFuncSetAttribute(handnet_mma, cudaFuncAttributeMaxDynamicSharedMemorySize, SMEM_SZ);
        attr_done = 1;
    }

    prep_frags<<<NPREP, 32>>>(W1, W2, W3, A1, A2, A3);
    const int nCTA = (Btot * 21 + RPC - 1) / RPC;
    handnet_mma<<<nCTA, 256, SMEM_SZ>>>(x, A1, b1, b2, b3, fcW, fcb,
                                        x3g, outg, Btot);
}